// round 15
// baseline (speedup 1.0000x reference)
#include <cuda_runtime.h>
#include <cuda_bf16.h>
#include <math.h>
#include <stdint.h>

#define NUM_BINS 15
#define C 100
#define THREADS 256

// Global scratch. Zeroed at load; the finalizing block re-zeros for next replay.
__device__ float        g_conf[NUM_BINS];
__device__ float        g_acc[NUM_BINS];
__device__ unsigned int g_done;

struct Stage {
    float4 v0, v1, v2;
    float  vt;     // scalar tail element (lanes b<4), else -80
    float  lv;     // true-class logit (lanes b==0), else 0
};

__global__ void __launch_bounds__(THREADS, 5) ece_kernel(
    const float* __restrict__ logits,
    const int*   __restrict__ labels32,   // int64 labels viewed as int32 pairs (LE low word)
    float* __restrict__ out,
    int n_rows, int n_groups, int total_blocks)
{
    __shared__ float s_conf[NUM_BINS];
    __shared__ float s_acc[NUM_BINS];

    const int tid = threadIdx.x;
    if (tid < NUM_BINS) { s_conf[tid] = 0.0f; s_acc[tid] = 0.0f; }
    __syncthreads();

    const int lane = tid & 31;
    const int a    = lane >> 3;          // row-in-group 0..3
    const int b    = lane & 7;           // lane-in-row  0..7
    const bool tail_lane = (b < 4);      // owns scalar element 96+b of its row
    const int warp_id   = (blockIdx.x * (THREADS / 32)) + (tid >> 5);
    const int num_warps = total_blocks * (THREADS / 32);

    // Stage: all loads for a group, including the dependent label->logit chain.
    // Runs one iteration ahead of compute, so the whole chain is latency-hidden.
    auto load_into = [&](Stage& r, int g) {
        int row = (g << 2) + a;
        const float* rowp = logits + (size_t)row * C;
        const float4* rp = reinterpret_cast<const float4*>(rowp);
        r.v0 = __ldg(&rp[b]);
        r.v1 = __ldg(&rp[b + 8]);
        r.v2 = __ldg(&rp[b + 16]);
        r.vt = tail_lane ? __ldg(rowp + 96 + b) : -80.0f;
        r.lv = 0.0f;
        if (b == 0) {
            int label = __ldg(labels32 + (size_t)row * 2);   // low word of int64
            label = min(max(label, 0), C - 1);
            r.lv = __ldg(rowp + label);                      // dependent, hidden
        }
    };

    // Compute: pure registers + shuffles + one smem atomic. No memory stalls.
    auto compute = [&](const Stage& q) {
        float e00 = __expf(q.v0.x), e01 = __expf(q.v0.y), e02 = __expf(q.v0.z), e03 = __expf(q.v0.w);
        float e10 = __expf(q.v1.x), e11 = __expf(q.v1.y), e12 = __expf(q.v1.z), e13 = __expf(q.v1.w);
        float e20 = __expf(q.v2.x), e21 = __expf(q.v2.y), e22 = __expf(q.v2.z), e23 = __expf(q.v2.w);
        float et  = __expf(q.vt);    // ~0 on non-tail lanes

        float em = fmaxf(fmaxf(fmaxf(e00, e01), fmaxf(e02, e03)),
                         fmaxf(fmaxf(e10, e11), fmaxf(e12, e13)));
        em = fmaxf(em, fmaxf(fmaxf(e20, e21), fmaxf(e22, e23)));
        em = fmaxf(em, et);

        float s = ((e00 + e01) + (e02 + e03))
                + ((e10 + e11) + (e12 + e13))
                + ((e20 + e21) + (e22 + e23))
                + et;

        #pragma unroll
        for (int o = 1; o <= 4; o <<= 1) {
            em = fmaxf(em, __shfl_xor_sync(0xffffffffu, em, o));
            s += __shfl_xor_sync(0xffffffffu, s, o);
        }

        if (b == 0) {
            float inv    = __frcp_rn(s);
            float max_p  = em * inv;              // in (0, 1]
            float pred_p = __expf(q.lv) * inv;
            int bin = min((int)(max_p * (float)NUM_BINS), NUM_BINS - 1);
            atomicAdd(&s_conf[bin], max_p);
            atomicAdd(&s_acc[bin],  pred_p);
        }
    };

    // ---- ping-pong depth-1 pipeline (renaming via unroll-2, no rotation MOVs) ----
    int  g    = warp_id;
    bool have = g < n_groups;
    Stage A, B;
    if (have) load_into(A, g);

    while (have) {
        int  gn = g + num_warps;
        bool hn = gn < n_groups;
        if (hn) load_into(B, gn);
        compute(A);
        g = gn; have = hn;
        if (!have) break;

        gn = g + num_warps;
        hn = gn < n_groups;
        if (hn) load_into(A, gn);
        compute(B);
        g = gn; have = hn;
    }

    // ---- remainder rows (n_rows % 4), block 0 only ----
    if (blockIdx.x == 0 && tid < 32) {
        int row = n_groups * 4 + lane;
        if (row < n_rows) {
            const float* rw = logits + (size_t)row * C;
            float em = 0.f, s = 0.f;
            for (int j = 0; j < C; j++) {
                float e = __expf(__ldg(rw + j));
                s += e; em = fmaxf(em, e);
            }
            int label = __ldg(labels32 + (size_t)row * 2);
            label = min(max(label, 0), C - 1);
            float pe  = __expf(__ldg(rw + label));
            float inv = __frcp_rn(s);
            float max_p = em * inv, pred_p = pe * inv;
            int bin = min((int)(max_p * (float)NUM_BINS), NUM_BINS - 1);
            atomicAdd(&s_conf[bin], max_p);
            atomicAdd(&s_acc[bin],  pred_p);
        }
    }

    __syncthreads();
    if (tid < NUM_BINS) {
        float c  = s_conf[tid];
        float aa = s_acc[tid];
        if (c  != 0.0f) atomicAdd(&g_conf[tid], c);
        if (aa != 0.0f) atomicAdd(&g_acc[tid],  aa);
    }
    __syncthreads();
    __threadfence();

    if (tid == 0) {
        unsigned int ticket = atomicAdd(&g_done, 1u);
        if (ticket == (unsigned int)(total_blocks - 1)) {
            __threadfence();
            float e = 0.0f;
            #pragma unroll
            for (int bb = 0; bb < NUM_BINS; bb++) {
                e += fabsf(g_conf[bb] - g_acc[bb]);
                g_conf[bb] = 0.0f;      // self-clean for next graph replay
                g_acc[bb]  = 0.0f;
            }
            out[0] = e / (float)n_rows;
            g_done = 0u;
        }
    }
}

extern "C" void kernel_launch(void* const* d_in, const int* in_sizes, int n_in,
                              void* d_out, int out_size)
{
    const float* logits   = (const float*)d_in[0];
    const int*   labels32 = (const int*)d_in[1];   // int64 viewed as int32 pairs
    float* out = (float*)d_out;

    int n_rows   = in_sizes[1];          // labels element count = N
    int n_groups = n_rows >> 2;          // full 4-row groups

    int blocks = 148 * 5;                // one wave at 5 CTAs/SM
    int max_blocks = (n_groups + (THREADS / 32) - 1) / (THREADS / 32);
    if (blocks > max_blocks) blocks = max_blocks;
    if (blocks < 1) blocks = 1;

    ece_kernel<<<blocks, THREADS>>>(logits, labels32, out, n_rows, n_groups, blocks);
}

// round 16
// speedup vs baseline: 1.1711x; 1.1711x over previous
#include <cuda_runtime.h>
#include <cuda_bf16.h>
#include <math.h>
#include <stdint.h>

#define NUM_BINS 15
#define C 100
#define THREADS 256

// Global scratch. Zeroed at load; the finalizing block re-zeros for next replay.
__device__ float        g_conf[NUM_BINS];
__device__ float        g_acc[NUM_BINS];
__device__ unsigned int g_done;

__global__ void __launch_bounds__(THREADS, 6) ece_kernel(
    const float* __restrict__ logits,
    const int*   __restrict__ labels32,   // int64 labels viewed as int32 pairs (LE low word)
    float* __restrict__ out,
    int n_rows, int n_groups, int total_blocks)
{
    __shared__ float s_conf[NUM_BINS];
    __shared__ float s_acc[NUM_BINS];

    const int tid = threadIdx.x;
    if (tid < NUM_BINS) { s_conf[tid] = 0.0f; s_acc[tid] = 0.0f; }
    __syncthreads();

    const int lane = tid & 31;
    const int a    = lane >> 3;          // row-in-group 0..3
    const int b    = lane & 7;           // lane-in-row  0..7
    const bool tail_lane = (b < 4);      // owns scalar element 96+b of its row
    const int warp_id   = (blockIdx.x * (THREADS / 32)) + (tid >> 5);
    const int num_warps = total_blocks * (THREADS / 32);

    // ---- software-pipelined grid-stride loop over 4-row groups (R11 body) ----
    int  g    = warp_id;
    bool have = g < n_groups;

    float4 v0, v1, v2;
    float  vt = -80.0f;                  // scalar tail element (exp(-80) ~ 0)
    int    lbl = 0;
    const float* rowp = logits;

    if (have) {
        int row = (g << 2) + a;
        rowp = logits + (size_t)row * C;
        const float4* rp = reinterpret_cast<const float4*>(rowp);
        v0 = __ldg(&rp[b]);
        v1 = __ldg(&rp[b + 8]);
        v2 = __ldg(&rp[b + 16]);
        if (tail_lane) vt = __ldg(rowp + 96 + b);
        lbl = __ldg(labels32 + (size_t)row * 2);   // low word of int64
    }

    while (have) {
        const int  gn = g + num_warps;
        const bool hn = gn < n_groups;

        // Prefetch next group: independent load burst in flight while computing.
        float4 w0, w1, w2;
        float  wt = -80.0f;
        int    lbln = 0;
        const float* rowpn = rowp;
        if (hn) {
            int rown = (gn << 2) + a;
            rowpn = logits + (size_t)rown * C;
            const float4* rpn = reinterpret_cast<const float4*>(rowpn);
            w0 = __ldg(&rpn[b]);
            w1 = __ldg(&rpn[b + 8]);
            w2 = __ldg(&rpn[b + 16]);
            if (tail_lane) wt = __ldg(rowpn + 96 + b);
            lbln = __ldg(labels32 + (size_t)rown * 2);
        }

        // ---- compute current group (exactly 100 exps per row) ----
        float e00 = __expf(v0.x), e01 = __expf(v0.y), e02 = __expf(v0.z), e03 = __expf(v0.w);
        float e10 = __expf(v1.x), e11 = __expf(v1.y), e12 = __expf(v1.z), e13 = __expf(v1.w);
        float e20 = __expf(v2.x), e21 = __expf(v2.y), e22 = __expf(v2.z), e23 = __expf(v2.w);
        float et  = __expf(vt);   // ~0 on non-tail lanes

        float em = fmaxf(fmaxf(fmaxf(e00, e01), fmaxf(e02, e03)),
                         fmaxf(fmaxf(e10, e11), fmaxf(e12, e13)));
        em = fmaxf(em, fmaxf(fmaxf(e20, e21), fmaxf(e22, e23)));
        em = fmaxf(em, et);

        float s = ((e00 + e01) + (e02 + e03))
                + ((e10 + e11) + (e12 + e13))
                + ((e20 + e21) + (e22 + e23))
                + et;

        // 3-level, 8-lane butterflies for max and sum
        #pragma unroll
        for (int o = 1; o <= 4; o <<= 1) {
            em = fmaxf(em, __shfl_xor_sync(0xffffffffu, em, o));
            s += __shfl_xor_sync(0xffffffffu, s, o);
        }

        if (b == 0) {
            int label = min(max(lbl, 0), C - 1);
            float lv = __ldg(rowp + label);       // L1 hit: row streamed last iter
            float inv    = __frcp_rn(s);
            float max_p  = em * inv;              // in (0, 1]
            float pred_p = __expf(lv) * inv;
            int bin = min((int)(max_p * (float)NUM_BINS), NUM_BINS - 1);
            atomicAdd(&s_conf[bin], max_p);
            atomicAdd(&s_acc[bin],  pred_p);
        }

        // rotate pipeline
        v0 = w0; v1 = w1; v2 = w2; vt = wt;
        lbl = lbln; rowp = rowpn;
        g = gn; have = hn;
    }

    // ---- remainder rows (n_rows % 4), block 0 only ----
    if (blockIdx.x == 0 && tid < 32) {
        int row = n_groups * 4 + lane;
        if (row < n_rows) {
            const float* rw = logits + (size_t)row * C;
            float em = 0.f, s = 0.f;
            for (int j = 0; j < C; j++) {
                float e = __expf(__ldg(rw + j));
                s += e; em = fmaxf(em, e);
            }
            int label = __ldg(labels32 + (size_t)row * 2);
            label = min(max(label, 0), C - 1);
            float pe  = __expf(__ldg(rw + label));
            float inv = __frcp_rn(s);
            float max_p = em * inv, pred_p = pe * inv;
            int bin = min((int)(max_p * (float)NUM_BINS), NUM_BINS - 1);
            atomicAdd(&s_conf[bin], max_p);
            atomicAdd(&s_acc[bin],  pred_p);
        }
    }

    __syncthreads();
    if (tid < NUM_BINS) {
        float c  = s_conf[tid];
        float aa = s_acc[tid];
        if (c  != 0.0f) atomicAdd(&g_conf[tid], c);
        if (aa != 0.0f) atomicAdd(&g_acc[tid],  aa);
    }
    __syncthreads();
    __threadfence();

    if (tid == 0) {
        unsigned int ticket = atomicAdd(&g_done, 1u);
        if (ticket == (unsigned int)(total_blocks - 1)) {
            __threadfence();
            float e = 0.0f;
            #pragma unroll
            for (int bb = 0; bb < NUM_BINS; bb++) {
                e += fabsf(g_conf[bb] - g_acc[bb]);
                g_conf[bb] = 0.0f;      // self-clean for next graph replay
                g_acc[bb]  = 0.0f;
            }
            out[0] = e / (float)n_rows;
            g_done = 0u;
        }
    }
}

extern "C" void kernel_launch(void* const* d_in, const int* in_sizes, int n_in,
                              void* d_out, int out_size)
{
    const float* logits   = (const float*)d_in[0];
    const int*   labels32 = (const int*)d_in[1];   // int64 viewed as int32 pairs
    float* out = (float*)d_out;

    int n_rows   = in_sizes[1];          // labels element count = N
    int n_groups = n_rows >> 2;          // full 4-row groups

    int blocks = 148 * 6;                // one wave at 6 CTAs/SM (42-reg budget)
    int max_blocks = (n_groups + (THREADS / 32) - 1) / (THREADS / 32);
    if (blocks > max_blocks) blocks = max_blocks;
    if (blocks < 1) blocks = 1;

    ece_kernel<<<blocks, THREADS>>>(logits, labels32, out, n_rows, n_groups, blocks);
}